// round 8
// baseline (speedup 1.0000x reference)
#include <cuda_runtime.h>

// out[b,pi,pj,h,w] = leaky_relu( (1/32) * sum_c x1[b,c,h,w] *
//                    x2_pad[b,c, h+2*pi-20, w+2*pj-20], 0.1 )
// B=4, C=32, H=32, W=1024, PATCH=21, DIL=2, PAD=20.
//
// h-pair scheme: block handles rows (h, h+2). Slice row h2 = h-20+2t serves
// BOTH (h, pi=t) and (h+2, pi=t-1), so every staged x2 slice and every
// X-register load feeds two accumulations.

#define WT     64      // w-tile per block
#define SLICE  112     // slice row stride in floats (need 104; 112 -> 16-bank shift)
#define CPH    8       // channels per pipeline stage (4 phases per t)
#define NBUF   2

__device__ __forceinline__ unsigned long long ffma2(unsigned long long a,
                                                    unsigned long long b,
                                                    unsigned long long c) {
    unsigned long long d;
    asm("fma.rn.f32x2 %0, %1, %2, %3;" : "=l"(d) : "l"(a), "l"(b), "l"(c));
    return d;
}

__device__ __forceinline__ void cp16(void* dst_smem, const void* src_gmem) {
    unsigned u = (unsigned)__cvta_generic_to_shared(dst_smem);
    asm volatile("cp.async.cg.shared.global [%0], [%1], 16;\n"
                 :: "r"(u), "l"(src_gmem));
}

extern __shared__ float smem[];

__global__ void __launch_bounds__(128, 4)
corr_kernel(const float* __restrict__ x1, const float* __restrict__ x2,
            float* __restrict__ out)
{
    const int w0   = blockIdx.x * WT;
    const int hp   = blockIdx.y;        // 16 h-pairs
    const int b    = blockIdx.z;
    const int h    = ((hp >> 1) << 2) + (hp & 1);   // pair rows: h, h+2
    const int tid  = threadIdx.x;
    const int wid  = tid >> 5;          // 4 warps
    const int lane = tid & 31;
    const int g    = lane & 15;         // w-group: 16 groups of 4 w's
    const int half = lane >> 4;         // 0: pj 0..10, 1: pj 10..20

    // staging map: 4 lanes per slice row (8 rows), stride-4 chunk interleave
    const int sr = lane >> 2;           // row 0..7 (channel within stage)
    const int sq = lane & 3;            // chunk phase 0..3

    float* x1s = smem;                                   // [2][32][WT]
    float* x2b = smem + 2 * 32 * WT + wid * (NBUF * CPH * SLICE);

    // ---- stage x1 tiles for both rows: 2 x 32 channels x 64 floats ----
    for (int f = tid; f < 2 * 32 * (WT / 4); f += 128) {
        const int h01 = f >> 9;         // 512 float4 chunks per row
        const int c   = (f >> 4) & 31;
        const int j   = f & 15;
        reinterpret_cast<float4*>(x1s)[f] = *reinterpret_cast<const float4*>(
            x1 + ((size_t)(b * 32 + c) * 32 + h + 2 * h01) * 1024 + w0 + 4 * j);
    }
    __syncthreads();

    const bool interior = (w0 != 0) && (w0 != 960);
    const int  wb = w0 - 20;

    // warp handles t = wid, wid+4, ... in [0,22)
    const int nt    = ((21 - wid) >> 2) + 1;   // 6,6,5,5
    const int total = nt * 4;                  // 4 phases of 8 channels per t

    auto do_stage = [&](int s) {
        const int t  = wid + ((s >> 2) << 2);
        const int ph = s & 3;
        const int h2 = h - 20 + 2 * t;
        float* dst = x2b + (s & 1) * (CPH * SLICE) + sr * SLICE;
        if (h2 >= 0 && h2 < 32) {
            const float* src =
                x2 + ((size_t)(b * 32 + ph * CPH + sr) * 32 + h2) * 1024;
            if (interior) {
                #pragma unroll
                for (int t2 = 0; t2 < 7; t2++) {
                    const int j = sq + 4 * t2;
                    if (j < 26) cp16(dst + 4 * j, src + wb + 4 * j);
                }
            } else {
                #pragma unroll
                for (int t2 = 0; t2 < 7; t2++) {
                    const int j = sq + 4 * t2;
                    if (j >= 26) break;
                    const int w2 = wb + 4 * j;
                    if (w2 >= 0 && w2 <= 1020) {
                        cp16(dst + 4 * j, src + w2);
                    } else {
                        float4 v;
                        v.x = (w2     >= 0 && w2     < 1024) ? src[w2]     : 0.f;
                        v.y = (w2 + 1 >= 0 && w2 + 1 < 1024) ? src[w2 + 1] : 0.f;
                        v.z = (w2 + 2 >= 0 && w2 + 2 < 1024) ? src[w2 + 2] : 0.f;
                        v.w = (w2 + 3 >= 0 && w2 + 3 < 1024) ? src[w2 + 3] : 0.f;
                        *reinterpret_cast<float4*>(dst + 4 * j) = v;
                    }
                }
            }
        } else {
            const float4 z = make_float4(0.f, 0.f, 0.f, 0.f);
            #pragma unroll
            for (int t2 = 0; t2 < 7; t2++) {
                const int j = sq + 4 * t2;
                if (j < 26) *reinterpret_cast<float4*>(dst + 4 * j) = z;
            }
        }
        asm volatile("cp.async.commit_group;\n" ::: "memory");
    };

    // acc[h01][p][q]: row h+2*h01, pj = p + 10*half, w-pair q (w = w0+4g+2q+{0,1})
    unsigned long long acc[2][11][2];
    #pragma unroll
    for (int a0 = 0; a0 < 2; a0++)
        #pragma unroll
        for (int p = 0; p < 11; p++)
            #pragma unroll
            for (int q = 0; q < 2; q++) acc[a0][p][q] = 0ull;

    const float* x1base = x1s + 4 * g;
    const float sp = 0.03125f;    // 1/32
    const float sn = 0.003125f;   // 0.1/32

    do_stage(0);

    for (int s = 0; s < total; s++) {
        if (s + 1 < total) {
            do_stage(s + 1);
            asm volatile("cp.async.wait_group 1;\n" ::: "memory");
        } else {
            asm volatile("cp.async.wait_group 0;\n" ::: "memory");
        }
        __syncwarp();

        // ---- compute stage s: 8 channels, both h rows ----
        const float* buf = x2b + (s & 1) * (CPH * SLICE);
        const int ph = s & 3;
        const float* x1p = x1base + ph * CPH * WT;
        const float* xwp = buf + 4 * g + 20 * half;

        #pragma unroll 2
        for (int c = 0; c < CPH; c++) {
            const ulonglong2 A0 =
                *reinterpret_cast<const ulonglong2*>(x1p + c * WT);
            const ulonglong2 A1 =
                *reinterpret_cast<const ulonglong2*>(x1p + c * WT + 32 * WT);

            ulonglong2 X[6];
            const float* bp = xwp + c * SLICE;
            #pragma unroll
            for (int j = 0; j < 6; j++)
                X[j] = *reinterpret_cast<const ulonglong2*>(bp + 4 * j);

            #pragma unroll
            for (int p = 0; p < 11; p++) {
                #pragma unroll
                for (int q = 0; q < 2; q++) {
                    const int k = p + q;                       // 0..11
                    const unsigned long long pk = (k & 1) ? X[k >> 1].y
                                                          : X[k >> 1].x;
                    const unsigned long long a0 = q ? A0.y : A0.x;
                    const unsigned long long a1 = q ? A1.y : A1.x;
                    acc[0][p][q] = ffma2(a0, pk, acc[0][p][q]);
                    acc[1][p][q] = ffma2(a1, pk, acc[1][p][q]);
                }
            }
        }

        // ---- per-t epilogue after last phase ----
        if ((s & 3) == 3) {
            const int t = wid + ((s >> 2) << 2);
            #pragma unroll
            for (int h01 = 0; h01 < 2; h01++) {
                const int pi = t - h01;
                if ((unsigned)pi <= 20u) {
                    const int ho = h + 2 * h01;
                    #pragma unroll
                    for (int p = 0; p < 11; p++) {
                        if (half == 1 && p == 0) continue;  // pj=10 dup by half A
                        const int pj = half ? (p + 10) : p;
                        float* op = out +
                            (((size_t)b * 441 + pi * 21 + pj) * 32 + ho) * 1024 +
                            w0 + 4 * g;
                        float2 f0 = *reinterpret_cast<float2*>(&acc[h01][p][0]);
                        float2 f1 = *reinterpret_cast<float2*>(&acc[h01][p][1]);
                        float4 v;
                        v.x = f0.x * ((f0.x < 0.f) ? sn : sp);
                        v.y = f0.y * ((f0.y < 0.f) ? sn : sp);
                        v.z = f1.x * ((f1.x < 0.f) ? sn : sp);
                        v.w = f1.y * ((f1.y < 0.f) ? sn : sp);
                        *reinterpret_cast<float4*>(op) = v;
                    }
                }
                #pragma unroll
                for (int p = 0; p < 11; p++) {
                    acc[h01][p][0] = 0ull;
                    acc[h01][p][1] = 0ull;
                }
            }
        }
        __syncwarp();   // buffer reads done before it is restaged
    }
}

extern "C" void kernel_launch(void* const* d_in, const int* in_sizes, int n_in,
                              void* d_out, int out_size) {
    const float* x1 = (const float*)d_in[0];
    const float* x2 = (const float*)d_in[1];
    float* out = (float*)d_out;

    const size_t smem_bytes =
        (size_t)(2 * 32 * WT + 4 * NBUF * CPH * SLICE) * sizeof(float);  // 45056 B
    cudaFuncSetAttribute(corr_kernel,
                         cudaFuncAttributeMaxDynamicSharedMemorySize,
                         (int)smem_bytes);

    dim3 grid(1024 / WT, 16, 4);   // (w-tiles, h-pairs, B)
    corr_kernel<<<grid, 128, smem_bytes>>>(x1, x2, out);
}

// round 9
// speedup vs baseline: 1.0693x; 1.0693x over previous
#include <cuda_runtime.h>

// out[b,pi,pj,h,w] = leaky_relu( (1/32) * sum_c x1[b,c,h,w] *
//                    x2_pad[b,c, h+2*pi-20, w+2*pj-20], 0.1 )
// B=4, C=32, H=32, W=1024, PATCH=21, DIL=2, PAD=20.
// R6 compute loop + cp.async.bulk (UBLKCP) staging with per-warp mbarrier
// double-buffer pipeline. Edge margins pre-zeroed once (bulk clips to valid range).

#define WT      128     // w-tile per block
#define SLICE   168     // slice row stride in floats (= window width)
#define CPH     4       // channels per pipeline stage (8 phases per pi)
#define NBUF    2
#define BUF_FLOATS (CPH * SLICE)   // 672

__device__ __forceinline__ unsigned long long ffma2(unsigned long long a,
                                                    unsigned long long b,
                                                    unsigned long long c) {
    unsigned long long d;
    asm("fma.rn.f32x2 %0, %1, %2, %3;" : "=l"(d) : "l"(a), "l"(b), "l"(c));
    return d;
}

__device__ __forceinline__ void mbar_init(unsigned mb) {
    asm volatile("mbarrier.init.shared.b64 [%0], 1;" :: "r"(mb) : "memory");
}
__device__ __forceinline__ void mbar_expect(unsigned mb, unsigned bytes) {
    asm volatile("mbarrier.arrive.expect_tx.shared.b64 _, [%0], %1;"
                 :: "r"(mb), "r"(bytes) : "memory");
}
__device__ __forceinline__ void bulk_g2s(unsigned dst, const void* src,
                                         unsigned bytes, unsigned mb) {
    asm volatile(
        "cp.async.bulk.shared::cta.global.mbarrier::complete_tx::bytes "
        "[%0], [%1], %2, [%3];"
        :: "r"(dst), "l"(src), "r"(bytes), "r"(mb) : "memory");
}
__device__ __forceinline__ void mbar_wait(unsigned mb, unsigned phase) {
    asm volatile(
        "{\n\t"
        ".reg .pred P;\n\t"
        "LAB_WAIT_%=:\n\t"
        "mbarrier.try_wait.parity.acquire.cta.shared::cta.b64 P, [%0], %1, 0x989680;\n\t"
        "@P bra.uni LAB_DONE_%=;\n\t"
        "bra.uni LAB_WAIT_%=;\n\t"
        "LAB_DONE_%=:\n\t"
        "}"
        :: "r"(mb), "r"(phase) : "memory");
}

extern __shared__ float smem[];

__global__ void __launch_bounds__(128, 4)
corr_kernel(const float* __restrict__ x1, const float* __restrict__ x2,
            float* __restrict__ out)
{
    const int w0   = blockIdx.x * WT;
    const int h    = blockIdx.y;
    const int b    = blockIdx.z;
    const int tid  = threadIdx.x;
    const int wid  = tid >> 5;          // 4 warps
    const int lane = tid & 31;
    const int g    = lane >> 1;         // w-group: 16 groups of 8 w's
    const int half = lane & 1;          // 0: pj 0..10, 1: pj 10..20

    float* x1s = smem;                                       // [32][WT]
    float* x2b = smem + 32 * WT + wid * (NBUF * BUF_FLOATS); // per-warp 2 buffers

    const unsigned smem_b  = (unsigned)__cvta_generic_to_shared(smem);
    const unsigned mb_base = smem_b +
        (unsigned)(32 * WT + 4 * NBUF * BUF_FLOATS) * 4u + (unsigned)wid * 16u;
    // mbar for buffer k of this warp: mb_base + k*8

    // ---- stage x1 tile: 32 channels x WT floats ----
    for (int f = tid; f < 32 * (WT / 4); f += 128) {
        const int c = f >> 5;
        const int j = f & 31;
        reinterpret_cast<float4*>(x1s)[f] = *reinterpret_cast<const float4*>(
            x1 + ((size_t)(b * 32 + c) * 32 + h) * 1024 + w0 + 4 * j);
    }
    __syncthreads();

    // per-block bulk-copy clipping (fixed for all stages)
    const int srcw = (w0 >= 20) ? (w0 - 20) : 0;            // first valid src float
    const int lo   = (w0 >= 20) ? 0 : (20 - w0);            // dst float offset
    const int hi   = (1044 - w0 < SLICE) ? (1044 - w0) : SLICE;
    const unsigned cpb = (unsigned)(hi - lo) * 4u;          // bytes per row

    if (lane == 0) { mbar_init(mb_base); mbar_init(mb_base + 8); }
    if (lo > 0 || hi < SLICE) {                             // zero margins once
        const float4 z = make_float4(0.f, 0.f, 0.f, 0.f);
        for (int j = lane; j < NBUF * BUF_FLOATS / 4; j += 32)
            reinterpret_cast<float4*>(x2b)[j] = z;
    }
    __syncwarp();

    const int total = (((20 - wid) >> 2) + 1) * 8;   // stages: 8 phases per pi

    auto do_stage = [&](int s) {
        const int pi = wid + ((s >> 3) << 2);
        const int h2 = h + 2 * pi - 20;
        float* dst = x2b + (s & 1) * BUF_FLOATS;
        if ((unsigned)h2 < 32u) {
            if (lane == 0) {
                const int ph = s & 7;
                const unsigned mb = mb_base + (unsigned)(s & 1) * 8u;
                mbar_expect(mb, cpb * CPH);
                const float* src =
                    x2 + ((size_t)(b * 32 + ph * CPH) * 32 + h2) * 1024 + srcw;
                const unsigned d =
                    smem_b + (unsigned)((int)(dst - smem) + lo) * 4u;
                #pragma unroll
                for (int r = 0; r < CPH; r++)
                    bulk_g2s(d + (unsigned)r * (SLICE * 4u),
                             src + (size_t)r * 32 * 1024, cpb, mb);
            }
        } else {
            const float4 z = make_float4(0.f, 0.f, 0.f, 0.f);
            for (int j = lane; j < BUF_FLOATS / 4; j += 32)
                reinterpret_cast<float4*>(dst)[j] = z;
        }
    };

    // acc[p][q]: pj = p + 10*half, w-pair q of this lane's 8 w's
    unsigned long long acc[11][4];
    #pragma unroll
    for (int p = 0; p < 11; p++)
        #pragma unroll
        for (int q = 0; q < 4; q++) acc[p][q] = 0ull;

    const float* x1base = x1s + 8 * g;
    const float sp = 0.03125f;    // 1/32
    const float sn = 0.003125f;   // 0.1/32

    unsigned pb0 = 0, pb1 = 0;    // consumer phase bits per buffer

    do_stage(0);

    for (int s = 0; s < total; s++) {
        if (s + 1 < total) do_stage(s + 1);

        // consume stage s
        {
            const int pi = wid + ((s >> 3) << 2);
            const int h2 = h + 2 * pi - 20;
            if ((unsigned)h2 < 32u) {
                if ((s & 1) == 0) { mbar_wait(mb_base,     pb0); pb0 ^= 1; }
                else              { mbar_wait(mb_base + 8, pb1); pb1 ^= 1; }
            }
        }
        __syncwarp();

        // ---- compute stage s: 4 channels ----
        const float* buf = x2b + (s & 1) * BUF_FLOATS;
        const int ph = s & 7;
        const float* x1p = x1base + ph * CPH * WT;
        const float* xwp = buf + 8 * g + 20 * half;

        #pragma unroll 2
        for (int c = 0; c < CPH; c++) {
            const float* x1row = x1p + c * WT;
            const ulonglong2 A0 = *reinterpret_cast<const ulonglong2*>(x1row);
            const ulonglong2 A1 = *reinterpret_cast<const ulonglong2*>(x1row + 4);
            const unsigned long long a[4] = {A0.x, A0.y, A1.x, A1.y};

            ulonglong2 X[7];
            const float* bp = xwp + c * SLICE;
            #pragma unroll
            for (int j = 0; j < 7; j++)
                X[j] = *reinterpret_cast<const ulonglong2*>(bp + 4 * j);

            #pragma unroll
            for (int p = 0; p < 11; p++) {
                #pragma unroll
                for (int q = 0; q < 4; q++) {
                    const int k = p + q;                       // 0..13
                    const unsigned long long pk = (k & 1) ? X[k >> 1].y
                                                          : X[k >> 1].x;
                    acc[p][q] = ffma2(a[q], pk, acc[p][q]);
                }
            }
        }

        // ---- per-pi epilogue after last phase ----
        if ((s & 7) == 7) {
            const int pi = wid + ((s >> 3) << 2);
            #pragma unroll
            for (int p = 0; p < 11; p++) {
                if (!(half == 1 && p == 0)) {      // pj=10 duplicated by half A
                    const int pj = half ? (p + 10) : p;
                    float* op = out +
                        (((size_t)b * 441 + pi * 21 + pj) * 32 + h) * 1024 +
                        w0 + 8 * g;
                    float v[8];
                    #pragma unroll
                    for (int q = 0; q < 4; q++) {
                        float2 fv = *reinterpret_cast<float2*>(&acc[p][q]);
                        v[2 * q]     = fv.x * ((fv.x < 0.f) ? sn : sp);
                        v[2 * q + 1] = fv.y * ((fv.y < 0.f) ? sn : sp);
                    }
                    *reinterpret_cast<float4*>(op) =
                        make_float4(v[0], v[1], v[2], v[3]);
                    *reinterpret_cast<float4*>(op + 4) =
                        make_float4(v[4], v[5], v[6], v[7]);
                }
                #pragma unroll
                for (int q = 0; q < 4; q++) acc[p][q] = 0ull;
            }
        }
        __syncwarp();   // buffer reads done before it is restaged
    }
}

extern "C" void kernel_launch(void* const* d_in, const int* in_sizes, int n_in,
                              void* d_out, int out_size) {
    const float* x1 = (const float*)d_in[0];
    const float* x2 = (const float*)d_in[1];
    float* out = (float*)d_out;

    // x1 tile + 4 warps * 2 buffers * 672 floats + 8 mbarriers
    const size_t smem_bytes =
        (size_t)(32 * WT + 4 * NBUF * BUF_FLOATS) * sizeof(float) + 64;  // 37952 B
    cudaFuncSetAttribute(corr_kernel,
                         cudaFuncAttributeMaxDynamicSharedMemorySize,
                         (int)smem_bytes);

    dim3 grid(1024 / WT, 32, 4);   // (w-tiles, H, B)
    corr_kernel<<<grid, 128, smem_bytes>>>(x1, x2, out);
}